// round 1
// baseline (speedup 1.0000x reference)
#include <cuda_runtime.h>
#include <cstdint>

#define DD 128
#define NMAX 100000
#define EMAX 1600000
#define RESC 0.2f
#define LNEPS 1e-5f

// ---------------- scratch (static device globals; no allocs allowed) --------
__device__ float g_t[NMAX * DD];    // GEMM input  (scaled / LN'd features)
__device__ float g_xw[NMAX * DD];   // GEMM output (pre-aggregation)
__device__ float g_agg[NMAX * DD];  // scatter-add accumulator
__device__ float g_h[NMAX * DD];    // layer output h
__device__ float g_rout[NMAX];      // rsqrt(deg_out)
__device__ float g_rin[NMAX];       // rsqrt(deg_in)

// ---------------- degree kernels --------------------------------------------
__global__ void degree_kernel(const int* __restrict__ src, const int* __restrict__ dst,
                              float* __restrict__ dout, float* __restrict__ din, int e) {
    int i = blockIdx.x * blockDim.x + threadIdx.x;
    if (i < e) {
        atomicAdd(dout + src[i], 1.0f);
        atomicAdd(din + dst[i], 1.0f);
    }
}

__global__ void rsqrt_kernel(float* __restrict__ a, float* __restrict__ b, int n) {
    int i = blockIdx.x * blockDim.x + threadIdx.x;
    if (i < n) {
        a[i] = rsqrtf(fmaxf(a[i], 1.0f));
        b[i] = rsqrtf(fmaxf(b[i], 1.0f));
    }
}

// ---------------- row scale: t = x * rout[row] ------------------------------
__global__ void scale_rows_kernel(const float* __restrict__ x, const float* __restrict__ r,
                                  float* __restrict__ o, int n) {
    int i = blockIdx.x * blockDim.x + threadIdx.x;  // float4 index
    if (i >= n * 32) return;
    int row = i >> 5;
    float s = __ldg(r + row);
    float4 v = ((const float4*)x)[i];
    v.x *= s; v.y *= s; v.z *= s; v.w *= s;
    ((float4*)o)[i] = v;
}

// ---------------- GEMM: C[n,128] = A[n,128] @ W[128,128] --------------------
// 128x128 output tile per block, 256 threads, 8x8 micro-tile, K staged by 8.
__global__ __launch_bounds__(256) void gemm128_kernel(
    const float* __restrict__ A, const float* __restrict__ W,
    float* __restrict__ C, int n)
{
    __shared__ float sA[8][128];  // [k][row]
    __shared__ float sW[8][128];  // [k][col]

    int tid = threadIdx.x;
    int row0 = blockIdx.x * 128;
    int ty = tid >> 4;   // 0..15 -> rows ty*8..ty*8+7
    int tx = tid & 15;   // 0..15 -> cols tx*8..tx*8+7

    float acc[8][8];
#pragma unroll
    for (int i = 0; i < 8; i++)
#pragma unroll
        for (int j = 0; j < 8; j++) acc[i][j] = 0.0f;

    int la_row = tid >> 1;
    int la_k   = (tid & 1) << 2;
    int lw_k   = tid >> 5;
    int lw_col = (tid & 31) << 2;

    for (int kk = 0; kk < 128; kk += 8) {
        float4 av = make_float4(0.f, 0.f, 0.f, 0.f);
        int grow = row0 + la_row;
        if (grow < n)
            av = *(const float4*)(A + (size_t)grow * DD + kk + la_k);
        sA[la_k + 0][la_row] = av.x;
        sA[la_k + 1][la_row] = av.y;
        sA[la_k + 2][la_row] = av.z;
        sA[la_k + 3][la_row] = av.w;

        *(float4*)&sW[lw_k][lw_col] =
            *(const float4*)(W + (size_t)(kk + lw_k) * DD + lw_col);
        __syncthreads();

#pragma unroll
        for (int k = 0; k < 8; k++) {
            float4 a0 = *(const float4*)&sA[k][ty * 8];
            float4 a1 = *(const float4*)&sA[k][ty * 8 + 4];
            float4 b0 = *(const float4*)&sW[k][tx * 8];
            float4 b1 = *(const float4*)&sW[k][tx * 8 + 4];
            float a[8] = {a0.x, a0.y, a0.z, a0.w, a1.x, a1.y, a1.z, a1.w};
            float b[8] = {b0.x, b0.y, b0.z, b0.w, b1.x, b1.y, b1.z, b1.w};
#pragma unroll
            for (int i = 0; i < 8; i++)
#pragma unroll
                for (int j = 0; j < 8; j++)
                    acc[i][j] = fmaf(a[i], b[j], acc[i][j]);
        }
        __syncthreads();
    }

#pragma unroll
    for (int i = 0; i < 8; i++) {
        int r = row0 + ty * 8 + i;
        if (r < n) {
            float4* cp = (float4*)(C + (size_t)r * DD + tx * 8);
            cp[0] = make_float4(acc[i][0], acc[i][1], acc[i][2], acc[i][3]);
            cp[1] = make_float4(acc[i][4], acc[i][5], acc[i][6], acc[i][7]);
        }
    }
}

// ---------------- edge scatter: agg[dst] += xw[src]; one warp per edge ------
__global__ void scatter_kernel(const int* __restrict__ src, const int* __restrict__ dst,
                               const float* __restrict__ xw, float* __restrict__ agg, int e)
{
    int eid = blockIdx.x * 8 + (threadIdx.x >> 5);
    if (eid >= e) return;
    int lane = threadIdx.x & 31;
    int s = __ldg(src + eid);
    int d = __ldg(dst + eid);
    float4 v = *((const float4*)(xw + (size_t)s * DD) + lane);
    float* p = agg + (size_t)d * DD + lane * 4;
    asm volatile("red.global.add.v4.f32 [%0], {%1,%2,%3,%4};"
                 :: "l"(p), "f"(v.x), "f"(v.y), "f"(v.z), "f"(v.w)
                 : "memory");
}

// ---------------- epilogue: out = agg*rin[row] + bias + 0.2*feat ------------
__global__ void epilogue_kernel(const float* __restrict__ agg, const float* __restrict__ rin,
                                const float* __restrict__ bias, const float* __restrict__ feat,
                                float* __restrict__ o, int n)
{
    int i = blockIdx.x * blockDim.x + threadIdx.x;  // float4 index
    if (i >= n * 32) return;
    int row = i >> 5;
    int c4 = i & 31;
    float s = __ldg(rin + row);
    float4 a = ((const float4*)agg)[i];
    float4 f = ((const float4*)feat)[i];
    float4 b = ((const float4*)bias)[c4];
    float4 r;
    r.x = fmaf(a.x, s, b.x) + RESC * f.x;
    r.y = fmaf(a.y, s, b.y) + RESC * f.y;
    r.z = fmaf(a.z, s, b.z) + RESC * f.z;
    r.w = fmaf(a.w, s, b.w) + RESC * f.w;
    ((float4*)o)[i] = r;
}

// ---------------- LN + ReLU + rout scale: warp per row ----------------------
__global__ void ln_relu_scale_kernel(const float* __restrict__ h,
                                     const float* __restrict__ g, const float* __restrict__ b,
                                     const float* __restrict__ rout, float* __restrict__ t, int n)
{
    int row = blockIdx.x * 8 + (threadIdx.x >> 5);
    if (row >= n) return;
    int lane = threadIdx.x & 31;

    float4 v = ((const float4*)(h + (size_t)row * DD))[lane];
    float sum = v.x + v.y + v.z + v.w;
#pragma unroll
    for (int o = 16; o > 0; o >>= 1) sum += __shfl_xor_sync(0xFFFFFFFFu, sum, o);
    float mu = sum * (1.0f / 128.0f);

    float dx = v.x - mu, dy = v.y - mu, dz = v.z - mu, dw = v.w - mu;
    float sq = dx * dx + dy * dy + dz * dz + dw * dw;
#pragma unroll
    for (int o = 16; o > 0; o >>= 1) sq += __shfl_xor_sync(0xFFFFFFFFu, sq, o);
    float inv = rsqrtf(sq * (1.0f / 128.0f) + LNEPS);

    float s = __ldg(rout + row);
    float4 gg = ((const float4*)g)[lane];
    float4 bb = ((const float4*)b)[lane];
    float4 r;
    r.x = fmaxf(fmaf(dx * inv, gg.x, bb.x), 0.0f) * s;
    r.y = fmaxf(fmaf(dy * inv, gg.y, bb.y), 0.0f) * s;
    r.z = fmaxf(fmaf(dz * inv, gg.z, bb.z), 0.0f) * s;
    r.w = fmaxf(fmaf(dw * inv, gg.w, bb.w), 0.0f) * s;
    ((float4*)(t + (size_t)row * DD))[lane] = r;
}

// ---------------- launch ------------------------------------------------------
extern "C" void kernel_launch(void* const* d_in, const int* in_sizes, int n_in,
                              void* d_out, int out_size)
{
    const int*   src     = (const int*)d_in[0];
    const int*   dst     = (const int*)d_in[1];
    const float* in_feat = (const float*)d_in[2];
    const float* W1      = (const float*)d_in[3];
    const float* b1      = (const float*)d_in[4];
    const float* W2      = (const float*)d_in[5];
    const float* b2      = (const float*)d_in[6];
    const float* ln1g    = (const float*)d_in[7];
    const float* ln1b    = (const float*)d_in[8];
    const float* ln2g    = (const float*)d_in[9];
    const float* ln2b    = (const float*)d_in[10];
    float* out = (float*)d_out;

    int E = in_sizes[0];
    int n = in_sizes[2] / DD;

    float *t, *xw, *agg, *h, *rout, *rin;
    cudaGetSymbolAddress((void**)&t,    g_t);
    cudaGetSymbolAddress((void**)&xw,   g_xw);
    cudaGetSymbolAddress((void**)&agg,  g_agg);
    cudaGetSymbolAddress((void**)&h,    g_h);
    cudaGetSymbolAddress((void**)&rout, g_rout);
    cudaGetSymbolAddress((void**)&rin,  g_rin);

    const int TB = 256;
    int gridE   = (E + TB - 1) / TB;
    int gridN   = (n + TB - 1) / TB;
    int gridV4  = (n * 32 + TB - 1) / TB;      // elementwise float4 grid
    int gridRow = (n + 7) / 8;                 // warp-per-row grid
    int gridEdW = (E + 7) / 8;                 // warp-per-edge grid
    int gridGemm = (n + 127) / 128;
    size_t featBytes = (size_t)n * DD * sizeof(float);

    // degrees (recomputed every call; deterministic)
    cudaMemsetAsync(rout, 0, n * sizeof(float));
    cudaMemsetAsync(rin,  0, n * sizeof(float));
    degree_kernel<<<gridE, TB>>>(src, dst, rout, rin, E);
    rsqrt_kernel<<<gridN, TB>>>(rout, rin, n);

    // ---- conv1: h = GCN(in_feat, W1, b1) + 0.2*in_feat
    scale_rows_kernel<<<gridV4, TB>>>(in_feat, rout, t, n);
    gemm128_kernel<<<gridGemm, TB>>>(t, W1, xw, n);
    cudaMemsetAsync(agg, 0, featBytes);
    scatter_kernel<<<gridEdW, TB>>>(src, dst, xw, agg, E);
    epilogue_kernel<<<gridV4, TB>>>(agg, rin, b1, in_feat, h, n);

    // ---- iter 1: h = GCN(relu(LN1(h)), W2, b2) + 0.2*in_feat
    ln_relu_scale_kernel<<<gridRow, TB>>>(h, ln1g, ln1b, rout, t, n);
    gemm128_kernel<<<gridGemm, TB>>>(t, W2, xw, n);
    cudaMemsetAsync(agg, 0, featBytes);
    scatter_kernel<<<gridEdW, TB>>>(src, dst, xw, agg, E);
    epilogue_kernel<<<gridV4, TB>>>(agg, rin, b2, in_feat, h, n);

    // ---- iter 2: out = GCN(relu(LN2(h)), W2, b2) + 0.2*in_feat
    ln_relu_scale_kernel<<<gridRow, TB>>>(h, ln2g, ln2b, rout, t, n);
    gemm128_kernel<<<gridGemm, TB>>>(t, W2, xw, n);
    cudaMemsetAsync(agg, 0, featBytes);
    scatter_kernel<<<gridEdW, TB>>>(src, dst, xw, agg, E);
    epilogue_kernel<<<gridV4, TB>>>(agg, rin, b2, in_feat, out, n);
}

// round 2
// speedup vs baseline: 1.7431x; 1.7431x over previous
#include <cuda_runtime.h>
#include <cstdint>

#define DD 128
#define NMAX 100000
#define EMAX 1600000
#define RESC 0.2f
#define LNEPS 1e-5f

// ---------------- scratch (static device globals; no allocs allowed) --------
__device__ float g_t[NMAX * DD];       // GEMM input (scaled / LN'd features)
__device__ float g_xw[NMAX * DD];      // GEMM output (pre-aggregation)
__device__ float g_rout[NMAX];         // rsqrt(deg_out)
__device__ float g_rin[NMAX];          // rsqrt(deg_in)
__device__ int   g_degout[NMAX];
__device__ int   g_degin[NMAX];
__device__ int   g_rowptr[NMAX + 1];   // CSR by dst
__device__ int   g_cursor[NMAX];
__device__ int   g_csrsrc[EMAX];       // src ids grouped by dst
__device__ int   g_bsums[256];         // scan block sums

// ---------------- degree (int) ----------------------------------------------
__global__ void degree_kernel(const int* __restrict__ src, const int* __restrict__ dst,
                              int* __restrict__ dout, int* __restrict__ din, int e) {
    int i = blockIdx.x * blockDim.x + threadIdx.x;
    if (i < e) {
        atomicAdd(dout + src[i], 1);
        atomicAdd(din + dst[i], 1);
    }
}

__global__ void rsqrt_kernel(const int* __restrict__ dout, const int* __restrict__ din,
                             float* __restrict__ rout, float* __restrict__ rin, int n) {
    int i = blockIdx.x * blockDim.x + threadIdx.x;
    if (i < n) {
        rout[i] = rsqrtf((float)max(dout[i], 1));
        rin[i]  = rsqrtf((float)max(din[i], 1));
    }
}

// ---------------- 3-kernel exclusive scan (1024 elems / block) --------------
__global__ void scan_block_kernel(const int* __restrict__ in, int* __restrict__ out,
                                  int* __restrict__ bsums, int n) {
    __shared__ int wsum[8];
    int t = threadIdx.x;
    int lane = t & 31, wid = t >> 5;
    int base = blockIdx.x * 1024 + t * 4;

    int v0 = (base + 0 < n) ? in[base + 0] : 0;
    int v1 = (base + 1 < n) ? in[base + 1] : 0;
    int v2 = (base + 2 < n) ? in[base + 2] : 0;
    int v3 = (base + 3 < n) ? in[base + 3] : 0;
    int tsum = v0 + v1 + v2 + v3;

    int x = tsum;  // inclusive warp scan
#pragma unroll
    for (int o = 1; o < 32; o <<= 1) {
        int y = __shfl_up_sync(0xFFFFFFFFu, x, o);
        if (lane >= o) x += y;
    }
    if (lane == 31) wsum[wid] = x;
    __syncthreads();
    if (wid == 0) {
        int w = (lane < 8) ? wsum[lane] : 0;
        int orig = w;
#pragma unroll
        for (int o = 1; o < 8; o <<= 1) {
            int y = __shfl_up_sync(0xFFFFFFFFu, w, o);
            if (lane >= o) w += y;
        }
        if (lane < 8) wsum[lane] = w - orig;  // exclusive warp offsets
    }
    __syncthreads();

    int texcl = wsum[wid] + x - tsum;  // exclusive prefix of this thread
    if (base + 0 < n) out[base + 0] = texcl;
    if (base + 1 < n) out[base + 1] = texcl + v0;
    if (base + 2 < n) out[base + 2] = texcl + v0 + v1;
    if (base + 3 < n) out[base + 3] = texcl + v0 + v1 + v2;
    if (t == 255) bsums[blockIdx.x] = wsum[7] + x;  // block total
}

__global__ void scan_spine_kernel(int* __restrict__ bsums, int nb) {
    __shared__ int sh[128];
    int t = threadIdx.x;
    int v = (t < nb) ? bsums[t] : 0;
    int orig = v;
#pragma unroll
    for (int o = 1; o < 128; o <<= 1) {
        sh[t] = v;
        __syncthreads();
        int y = (t >= o) ? sh[t - o] : 0;
        __syncthreads();
        v += y;
    }
    if (t < nb) bsums[t] = v - orig;  // exclusive
}

__global__ void scan_add_kernel(int* __restrict__ out, const int* __restrict__ bsums,
                                int n, int e) {
    int base = blockIdx.x * 1024 + threadIdx.x * 4;
    int add = bsums[blockIdx.x];
#pragma unroll
    for (int i = 0; i < 4; i++)
        if (base + i < n) out[base + i] += add;
    if (blockIdx.x == 0 && threadIdx.x == 0) out[n] = e;
}

// ---------------- CSR fill ---------------------------------------------------
__global__ void cursor_copy_kernel(int* __restrict__ cur, const int* __restrict__ rp, int n) {
    int i = blockIdx.x * blockDim.x + threadIdx.x;
    if (i < n) cur[i] = rp[i];
}

__global__ void csr_fill_kernel(const int* __restrict__ src, const int* __restrict__ dst,
                                int* __restrict__ cursor, int* __restrict__ csr, int e) {
    int i = blockIdx.x * blockDim.x + threadIdx.x;
    if (i < e) {
        int p = atomicAdd(cursor + dst[i], 1);
        csr[p] = src[i];
    }
}

// ---------------- GEMM: C[n,128] = (rs ? diag(rs) : I) A @ W ----------------
// 128x128 tile / 256 threads / 8x8 micro-tile, double-buffered smem.
__global__ __launch_bounds__(256) void gemm128_kernel(
    const float* __restrict__ A, const float* __restrict__ W,
    const float* __restrict__ rs, float* __restrict__ C, int n)
{
    __shared__ float sA[2][8][128];
    __shared__ float sW[2][8][128];

    int tid = threadIdx.x;
    int row0 = blockIdx.x * 128;
    int ty = tid >> 4, tx = tid & 15;

    int la_row = tid >> 1;
    int la_k   = (tid & 1) << 2;
    int lw_k   = tid >> 5;
    int lw_col = (tid & 31) << 2;

    int grow = row0 + la_row;
    bool rok = grow < n;
    float scale = 1.0f;
    if (rs != nullptr && rok) scale = __ldg(rs + grow);
    const float* Arow = A + (size_t)grow * DD + la_k;
    const float* Wp = W + (size_t)lw_k * DD + lw_col;

    float4 av = make_float4(0.f, 0.f, 0.f, 0.f);
    if (rok) av = *(const float4*)Arow;
    av.x *= scale; av.y *= scale; av.z *= scale; av.w *= scale;
    float4 wv = *(const float4*)Wp;

    sA[0][la_k + 0][la_row] = av.x;
    sA[0][la_k + 1][la_row] = av.y;
    sA[0][la_k + 2][la_row] = av.z;
    sA[0][la_k + 3][la_row] = av.w;
    *(float4*)&sW[0][lw_k][lw_col] = wv;
    __syncthreads();

    float acc[8][8];
#pragma unroll
    for (int i = 0; i < 8; i++)
#pragma unroll
        for (int j = 0; j < 8; j++) acc[i][j] = 0.0f;

#pragma unroll
    for (int s = 0; s < 16; s++) {
        int cur = s & 1;
        float4 pav = make_float4(0.f, 0.f, 0.f, 0.f), pwv;
        if (s < 15) {
            int kk = (s + 1) * 8;
            if (rok) pav = *(const float4*)(Arow + kk);
            pav.x *= scale; pav.y *= scale; pav.z *= scale; pav.w *= scale;
            pwv = *(const float4*)(Wp + (size_t)kk * DD);
        }
#pragma unroll
        for (int k = 0; k < 8; k++) {
            float4 a0 = *(const float4*)&sA[cur][k][ty * 8];
            float4 a1 = *(const float4*)&sA[cur][k][ty * 8 + 4];
            float4 b0 = *(const float4*)&sW[cur][k][tx * 8];
            float4 b1 = *(const float4*)&sW[cur][k][tx * 8 + 4];
            float a[8] = {a0.x, a0.y, a0.z, a0.w, a1.x, a1.y, a1.z, a1.w};
            float b[8] = {b0.x, b0.y, b0.z, b0.w, b1.x, b1.y, b1.z, b1.w};
#pragma unroll
            for (int i = 0; i < 8; i++)
#pragma unroll
                for (int j = 0; j < 8; j++)
                    acc[i][j] = fmaf(a[i], b[j], acc[i][j]);
        }
        if (s < 15) {
            int nb = cur ^ 1;
            sA[nb][la_k + 0][la_row] = pav.x;
            sA[nb][la_k + 1][la_row] = pav.y;
            sA[nb][la_k + 2][la_row] = pav.z;
            sA[nb][la_k + 3][la_row] = pav.w;
            *(float4*)&sW[nb][lw_k][lw_col] = pwv;
            __syncthreads();
        }
    }

#pragma unroll
    for (int i = 0; i < 8; i++) {
        int r = row0 + ty * 8 + i;
        if (r < n) {
            float4* cp = (float4*)(C + (size_t)r * DD + tx * 8);
            cp[0] = make_float4(acc[i][0], acc[i][1], acc[i][2], acc[i][3]);
            cp[1] = make_float4(acc[i][4], acc[i][5], acc[i][6], acc[i][7]);
        }
    }
}

// ---------------- fused CSR aggregate + epilogue [+ LN/ReLU/rout] -----------
// One warp per dst row; row lives entirely in 32 lanes x float4.
template <bool DO_LN>
__global__ void agg_kernel(const int* __restrict__ rowptr, const int* __restrict__ csr,
                           const float* __restrict__ xw, const float* __restrict__ rin,
                           const float* __restrict__ bias, const float* __restrict__ feat,
                           const float* __restrict__ lng, const float* __restrict__ lnb,
                           const float* __restrict__ rout, float* __restrict__ o, int n)
{
    int row = blockIdx.x * 8 + (threadIdx.x >> 5);
    if (row >= n) return;
    int lane = threadIdx.x & 31;

    int beg = __ldg(rowptr + row);
    int end = __ldg(rowptr + row + 1);

    const float4* xwv = (const float4*)xw;
    float4 a0 = make_float4(0.f, 0.f, 0.f, 0.f);
    float4 a1 = make_float4(0.f, 0.f, 0.f, 0.f);
    int e = beg;
    for (; e + 2 <= end; e += 2) {
        int s0 = __ldg(csr + e);
        int s1 = __ldg(csr + e + 1);
        float4 v0 = __ldg(xwv + (size_t)s0 * 32 + lane);
        float4 v1 = __ldg(xwv + (size_t)s1 * 32 + lane);
        a0.x += v0.x; a0.y += v0.y; a0.z += v0.z; a0.w += v0.w;
        a1.x += v1.x; a1.y += v1.y; a1.z += v1.z; a1.w += v1.w;
    }
    if (e < end) {
        int s0 = __ldg(csr + e);
        float4 v0 = __ldg(xwv + (size_t)s0 * 32 + lane);
        a0.x += v0.x; a0.y += v0.y; a0.z += v0.z; a0.w += v0.w;
    }
    float4 acc = make_float4(a0.x + a1.x, a0.y + a1.y, a0.z + a1.z, a0.w + a1.w);

    // epilogue: h = acc * rin[row] + bias + 0.2*feat
    float s = __ldg(rin + row);
    float4 bb = ((const float4*)bias)[lane];
    float4 f = __ldg((const float4*)feat + (size_t)row * 32 + lane);
    float4 h;
    h.x = fmaf(acc.x, s, bb.x) + RESC * f.x;
    h.y = fmaf(acc.y, s, bb.y) + RESC * f.y;
    h.z = fmaf(acc.z, s, bb.z) + RESC * f.z;
    h.w = fmaf(acc.w, s, bb.w) + RESC * f.w;

    if (!DO_LN) {
        ((float4*)(o + (size_t)row * DD))[lane] = h;
        return;
    }

    // LN + ReLU + rout scale (produces next GEMM input)
    float sum = h.x + h.y + h.z + h.w;
#pragma unroll
    for (int off = 16; off > 0; off >>= 1) sum += __shfl_xor_sync(0xFFFFFFFFu, sum, off);
    float mu = sum * (1.0f / 128.0f);

    float dx = h.x - mu, dy = h.y - mu, dz = h.z - mu, dw = h.w - mu;
    float sq = dx * dx + dy * dy + dz * dz + dw * dw;
#pragma unroll
    for (int off = 16; off > 0; off >>= 1) sq += __shfl_xor_sync(0xFFFFFFFFu, sq, off);
    float inv = rsqrtf(sq * (1.0f / 128.0f) + LNEPS);

    float ro = __ldg(rout + row);
    float4 gg = ((const float4*)lng)[lane];
    float4 lb = ((const float4*)lnb)[lane];
    float4 r;
    r.x = fmaxf(fmaf(dx * inv, gg.x, lb.x), 0.0f) * ro;
    r.y = fmaxf(fmaf(dy * inv, gg.y, lb.y), 0.0f) * ro;
    r.z = fmaxf(fmaf(dz * inv, gg.z, lb.z), 0.0f) * ro;
    r.w = fmaxf(fmaf(dw * inv, gg.w, lb.w), 0.0f) * ro;
    ((float4*)(o + (size_t)row * DD))[lane] = r;
}

// ---------------- launch ------------------------------------------------------
extern "C" void kernel_launch(void* const* d_in, const int* in_sizes, int n_in,
                              void* d_out, int out_size)
{
    const int*   src     = (const int*)d_in[0];
    const int*   dst     = (const int*)d_in[1];
    const float* in_feat = (const float*)d_in[2];
    const float* W1      = (const float*)d_in[3];
    const float* b1      = (const float*)d_in[4];
    const float* W2      = (const float*)d_in[5];
    const float* b2      = (const float*)d_in[6];
    const float* ln1g    = (const float*)d_in[7];
    const float* ln1b    = (const float*)d_in[8];
    const float* ln2g    = (const float*)d_in[9];
    const float* ln2b    = (const float*)d_in[10];
    float* out = (float*)d_out;

    int E = in_sizes[0];
    int n = in_sizes[2] / DD;

    float *t, *xw, *rout, *rin;
    int *degout, *degin, *rowptr, *cursor, *csrsrc, *bsums;
    cudaGetSymbolAddress((void**)&t,      g_t);
    cudaGetSymbolAddress((void**)&xw,     g_xw);
    cudaGetSymbolAddress((void**)&rout,   g_rout);
    cudaGetSymbolAddress((void**)&rin,    g_rin);
    cudaGetSymbolAddress((void**)&degout, g_degout);
    cudaGetSymbolAddress((void**)&degin,  g_degin);
    cudaGetSymbolAddress((void**)&rowptr, g_rowptr);
    cudaGetSymbolAddress((void**)&cursor, g_cursor);
    cudaGetSymbolAddress((void**)&csrsrc, g_csrsrc);
    cudaGetSymbolAddress((void**)&bsums,  g_bsums);

    const int TB = 256;
    int gridE    = (E + TB - 1) / TB;
    int gridN    = (n + TB - 1) / TB;
    int gridRow  = (n + 7) / 8;
    int gridGemm = (n + 127) / 128;
    int gridScan = (n + 1023) / 1024;

    // ---- graph preprocessing (per call; deterministic up to fp atomic order)
    cudaMemsetAsync(degout, 0, n * sizeof(int));
    cudaMemsetAsync(degin,  0, n * sizeof(int));
    degree_kernel<<<gridE, TB>>>(src, dst, degout, degin, E);
    rsqrt_kernel<<<gridN, TB>>>(degout, degin, rout, rin, n);
    scan_block_kernel<<<gridScan, 256>>>(degin, rowptr, bsums, n);
    scan_spine_kernel<<<1, 128>>>(bsums, gridScan);
    scan_add_kernel<<<gridScan, 256>>>(rowptr, bsums, n, E);
    cursor_copy_kernel<<<gridN, TB>>>(cursor, rowptr, n);
    csr_fill_kernel<<<gridE, TB>>>(src, dst, cursor, csrsrc, E);

    // ---- conv1: h = GCN(in_feat,W1,b1)+0.2x ; fused LN1+ReLU+rout -> t
    gemm128_kernel<<<gridGemm, TB>>>(in_feat, W1, rout, xw, n);
    agg_kernel<true><<<gridRow, TB>>>(rowptr, csrsrc, xw, rin, b1, in_feat,
                                      ln1g, ln1b, rout, t, n);

    // ---- conv2: fused LN2+ReLU+rout -> t
    gemm128_kernel<<<gridGemm, TB>>>(t, W2, nullptr, xw, n);
    agg_kernel<true><<<gridRow, TB>>>(rowptr, csrsrc, xw, rin, b2, in_feat,
                                      ln2g, ln2b, rout, t, n);

    // ---- conv3: final epilogue -> out
    gemm128_kernel<<<gridGemm, TB>>>(t, W2, nullptr, xw, n);
    agg_kernel<false><<<gridRow, TB>>>(rowptr, csrsrc, xw, rin, b2, in_feat,
                                       nullptr, nullptr, nullptr, out, n);
}

// round 3
// speedup vs baseline: 3.0495x; 1.7494x over previous
#include <cuda_runtime.h>
#include <cstdint>

#define DD 128
#define NMAX 100000
#define EMAX 1600000
#define RESC 0.2f
#define LNEPS 1e-5f

// ---------------- scratch (static device globals; no allocs allowed) --------
__device__ float g_t[NMAX * DD];       // GEMM input (LN'd features)
__device__ float g_xw[NMAX * DD];      // GEMM output (pre-aggregation)
__device__ float g_rout[NMAX];         // rsqrt(deg_out)
__device__ float g_rin[NMAX];          // rsqrt(deg_in)
__device__ int   g_degout[NMAX];
__device__ int   g_degin[NMAX];
__device__ int   g_rowptr[NMAX + 1];   // CSR by dst
__device__ int   g_cursor[NMAX];
__device__ int   g_csrsrc[EMAX];       // src ids grouped by dst
__device__ int   g_bsums[256];         // scan block sums

// ---------------- degree (int) ----------------------------------------------
__global__ void degree_kernel(const int* __restrict__ src, const int* __restrict__ dst,
                              int* __restrict__ dout, int* __restrict__ din, int e) {
    int i = blockIdx.x * blockDim.x + threadIdx.x;
    if (i < e) {
        atomicAdd(dout + src[i], 1);
        atomicAdd(din + dst[i], 1);
    }
}

__global__ void rsqrt_kernel(const int* __restrict__ dout, const int* __restrict__ din,
                             float* __restrict__ rout, float* __restrict__ rin, int n) {
    int i = blockIdx.x * blockDim.x + threadIdx.x;
    if (i < n) {
        rout[i] = rsqrtf((float)max(dout[i], 1));
        rin[i]  = rsqrtf((float)max(din[i], 1));
    }
}

// ---------------- 3-kernel exclusive scan (1024 elems / block) --------------
__global__ void scan_block_kernel(const int* __restrict__ in, int* __restrict__ out,
                                  int* __restrict__ bsums, int n) {
    __shared__ int wsum[8];
    int t = threadIdx.x;
    int lane = t & 31, wid = t >> 5;
    int base = blockIdx.x * 1024 + t * 4;

    int v0 = (base + 0 < n) ? in[base + 0] : 0;
    int v1 = (base + 1 < n) ? in[base + 1] : 0;
    int v2 = (base + 2 < n) ? in[base + 2] : 0;
    int v3 = (base + 3 < n) ? in[base + 3] : 0;
    int tsum = v0 + v1 + v2 + v3;

    int x = tsum;
#pragma unroll
    for (int o = 1; o < 32; o <<= 1) {
        int y = __shfl_up_sync(0xFFFFFFFFu, x, o);
        if (lane >= o) x += y;
    }
    if (lane == 31) wsum[wid] = x;
    __syncthreads();
    if (wid == 0) {
        int w = (lane < 8) ? wsum[lane] : 0;
        int orig = w;
#pragma unroll
        for (int o = 1; o < 8; o <<= 1) {
            int y = __shfl_up_sync(0xFFFFFFFFu, w, o);
            if (lane >= o) w += y;
        }
        if (lane < 8) wsum[lane] = w - orig;
    }
    __syncthreads();

    int texcl = wsum[wid] + x - tsum;
    if (base + 0 < n) out[base + 0] = texcl;
    if (base + 1 < n) out[base + 1] = texcl + v0;
    if (base + 2 < n) out[base + 2] = texcl + v0 + v1;
    if (base + 3 < n) out[base + 3] = texcl + v0 + v1 + v2;
    if (t == 255) bsums[blockIdx.x] = wsum[7] + x;
}

__global__ void scan_spine_kernel(int* __restrict__ bsums, int nb) {
    __shared__ int sh[128];
    int t = threadIdx.x;
    int v = (t < nb) ? bsums[t] : 0;
    int orig = v;
#pragma unroll
    for (int o = 1; o < 128; o <<= 1) {
        sh[t] = v;
        __syncthreads();
        int y = (t >= o) ? sh[t - o] : 0;
        __syncthreads();
        v += y;
    }
    if (t < nb) bsums[t] = v - orig;
}

// adds spine offsets; also emits cursor = rowptr copy for csr_fill
__global__ void scan_add_kernel(int* __restrict__ out, int* __restrict__ cursor,
                                const int* __restrict__ bsums, int n, int e) {
    int base = blockIdx.x * 1024 + threadIdx.x * 4;
    int add = bsums[blockIdx.x];
#pragma unroll
    for (int i = 0; i < 4; i++)
        if (base + i < n) {
            int v = out[base + i] + add;
            out[base + i] = v;
            cursor[base + i] = v;
        }
    if (blockIdx.x == 0 && threadIdx.x == 0) out[n] = e;
}

__global__ void csr_fill_kernel(const int* __restrict__ src, const int* __restrict__ dst,
                                int* __restrict__ cursor, int* __restrict__ csr, int e) {
    int i = blockIdx.x * blockDim.x + threadIdx.x;
    if (i < e) {
        int p = atomicAdd(cursor + dst[i], 1);
        csr[p] = src[i];
    }
}

// ---------------- TF32 tensor-core GEMM -------------------------------------
// C[n,128] = (rs ? diag(rs) : I) A[n,128] @ W[128,128]
// 128x128 block tile, 256 threads (8 warps, 4x2), warp tile 32x64,
// mma.m16n8k8.tf32, K staged by 16, double-buffered smem (stride-136 pad).
#define SST 136

__device__ __forceinline__ uint32_t f2tf32(float x) {
    uint32_t r;
    asm("cvt.rna.tf32.f32 %0, %1;" : "=r"(r) : "f"(x));
    return r;
}

__global__ __launch_bounds__(256) void gemm_tf32_kernel(
    const float* __restrict__ A, const float* __restrict__ W,
    const float* __restrict__ rs, float* __restrict__ C, int n)
{
    __shared__ uint32_t sA[2][16 * SST];  // [k][m], padded
    __shared__ uint32_t sW[2][16 * SST];  // [k][n], padded

    int tid = threadIdx.x;
    int lane = tid & 31;
    int wrp = tid >> 5;
    int wm = wrp & 3;        // m warp tile: rows wm*32
    int wn = wrp >> 2;       // n warp tile: cols wn*64
    int tig = lane & 3;
    int gid = lane >> 2;
    int row0 = blockIdx.x * 128;

    // staging indices: A rows handled by this thread
    int ar0 = tid >> 2;             // 0..63
    int ar1 = ar0 + 64;
    int ak0 = (tid & 3) << 2;       // k offset {0,4,8,12}
    int wk0 = tid >> 5;             // 0..7
    int wk1 = wk0 + 8;
    int wc4 = (tid & 31) << 2;      // col {0,4,...,124}

    bool rok0 = (row0 + ar0) < n;
    bool rok1 = (row0 + ar1) < n;
    float sc0 = 1.0f, sc1 = 1.0f;
    if (rs != nullptr) {
        if (rok0) sc0 = __ldg(rs + row0 + ar0);
        if (rok1) sc1 = __ldg(rs + row0 + ar1);
    }
    const float* Ap0 = A + (size_t)(row0 + ar0) * DD + ak0;
    const float* Ap1 = A + (size_t)(row0 + ar1) * DD + ak0;
    const float* Wp0 = W + (size_t)wk0 * DD + wc4;
    const float* Wp1 = W + (size_t)wk1 * DD + wc4;

    float acc[2][8][4];
#pragma unroll
    for (int i = 0; i < 2; i++)
#pragma unroll
        for (int j = 0; j < 8; j++)
#pragma unroll
            for (int k = 0; k < 4; k++) acc[i][j][k] = 0.0f;

    float4 a0 = make_float4(0.f, 0.f, 0.f, 0.f), a1 = a0;
    if (rok0) a0 = *(const float4*)Ap0;
    if (rok1) a1 = *(const float4*)Ap1;
    float4 w0 = *(const float4*)Wp0;
    float4 w1 = *(const float4*)Wp1;

    // store stage 0
    {
        uint32_t* pA = &sA[0][0];
        pA[(ak0 + 0) * SST + ar0] = f2tf32(a0.x * sc0);
        pA[(ak0 + 1) * SST + ar0] = f2tf32(a0.y * sc0);
        pA[(ak0 + 2) * SST + ar0] = f2tf32(a0.z * sc0);
        pA[(ak0 + 3) * SST + ar0] = f2tf32(a0.w * sc0);
        pA[(ak0 + 0) * SST + ar1] = f2tf32(a1.x * sc1);
        pA[(ak0 + 1) * SST + ar1] = f2tf32(a1.y * sc1);
        pA[(ak0 + 2) * SST + ar1] = f2tf32(a1.z * sc1);
        pA[(ak0 + 3) * SST + ar1] = f2tf32(a1.w * sc1);
        uint32_t* pW = &sW[0][0];
        uint4 u0 = make_uint4(f2tf32(w0.x), f2tf32(w0.y), f2tf32(w0.z), f2tf32(w0.w));
        uint4 u1 = make_uint4(f2tf32(w1.x), f2tf32(w1.y), f2tf32(w1.z), f2tf32(w1.w));
        *(uint4*)&pW[wk0 * SST + wc4] = u0;
        *(uint4*)&pW[wk1 * SST + wc4] = u1;
    }
    __syncthreads();

#pragma unroll
    for (int s = 0; s < 8; s++) {
        int cur = s & 1;
        if (s < 7) {
            int kb = (s + 1) * 16;
            a0 = make_float4(0.f, 0.f, 0.f, 0.f); a1 = a0;
            if (rok0) a0 = *(const float4*)(Ap0 + kb);
            if (rok1) a1 = *(const float4*)(Ap1 + kb);
            w0 = *(const float4*)(Wp0 + (size_t)kb * DD);
            w1 = *(const float4*)(Wp1 + (size_t)kb * DD);
        }

        const uint32_t* pA = &sA[cur][0];
        const uint32_t* pW = &sW[cur][0];
#pragma unroll
        for (int ks = 0; ks < 2; ks++) {
            int k0 = ks * 8;
            uint32_t af[2][4];
#pragma unroll
            for (int mt = 0; mt < 2; mt++) {
                int rb = wm * 32 + mt * 16 + gid;
                af[mt][0] = pA[(k0 + tig) * SST + rb];
                af[mt][1] = pA[(k0 + tig) * SST + rb + 8];
                af[mt][2] = pA[(k0 + tig + 4) * SST + rb];
                af[mt][3] = pA[(k0 + tig + 4) * SST + rb + 8];
            }
#pragma unroll
            for (int nt = 0; nt < 8; nt++) {
                int cb = wn * 64 + nt * 8 + gid;
                uint32_t b0 = pW[(k0 + tig) * SST + cb];
                uint32_t b1 = pW[(k0 + tig + 4) * SST + cb];
#pragma unroll
                for (int mt = 0; mt < 2; mt++) {
                    asm volatile(
                        "mma.sync.aligned.m16n8k8.row.col.f32.tf32.tf32.f32 "
                        "{%0,%1,%2,%3}, {%4,%5,%6,%7}, {%8,%9}, {%0,%1,%2,%3};"
                        : "+f"(acc[mt][nt][0]), "+f"(acc[mt][nt][1]),
                          "+f"(acc[mt][nt][2]), "+f"(acc[mt][nt][3])
                        : "r"(af[mt][0]), "r"(af[mt][1]), "r"(af[mt][2]), "r"(af[mt][3]),
                          "r"(b0), "r"(b1));
                }
            }
        }

        if (s < 7) {
            int nb = cur ^ 1;
            uint32_t* qA = &sA[nb][0];
            qA[(ak0 + 0) * SST + ar0] = f2tf32(a0.x * sc0);
            qA[(ak0 + 1) * SST + ar0] = f2tf32(a0.y * sc0);
            qA[(ak0 + 2) * SST + ar0] = f2tf32(a0.z * sc0);
            qA[(ak0 + 3) * SST + ar0] = f2tf32(a0.w * sc0);
            qA[(ak0 + 0) * SST + ar1] = f2tf32(a1.x * sc1);
            qA[(ak0 + 1) * SST + ar1] = f2tf32(a1.y * sc1);
            qA[(ak0 + 2) * SST + ar1] = f2tf32(a1.z * sc1);
            qA[(ak0 + 3) * SST + ar1] = f2tf32(a1.w * sc1);
            uint32_t* qW = &sW[nb][0];
            uint4 u0 = make_uint4(f2tf32(w0.x), f2tf32(w0.y), f2tf32(w0.z), f2tf32(w0.w));
            uint4 u1 = make_uint4(f2tf32(w1.x), f2tf32(w1.y), f2tf32(w1.z), f2tf32(w1.w));
            *(uint4*)&qW[wk0 * SST + wc4] = u0;
            *(uint4*)&qW[wk1 * SST + wc4] = u1;
            __syncthreads();
        }
    }

    // writeout
#pragma unroll
    for (int mt = 0; mt < 2; mt++) {
        int r0 = row0 + wm * 32 + mt * 16 + gid;
        int r1 = r0 + 8;
#pragma unroll
        for (int nt = 0; nt < 8; nt++) {
            int col = wn * 64 + nt * 8 + tig * 2;
            if (r0 < n)
                *(float2*)(C + (size_t)r0 * DD + col) =
                    make_float2(acc[mt][nt][0], acc[mt][nt][1]);
            if (r1 < n)
                *(float2*)(C + (size_t)r1 * DD + col) =
                    make_float2(acc[mt][nt][2], acc[mt][nt][3]);
        }
    }
}

// ---------------- fused CSR aggregate + epilogue [+ LN/ReLU/rout] -----------
template <bool DO_LN>
__global__ void agg_kernel(const int* __restrict__ rowptr, const int* __restrict__ csr,
                           const float* __restrict__ xw, const float* __restrict__ rin,
                           const float* __restrict__ bias, const float* __restrict__ feat,
                           const float* __restrict__ lng, const float* __restrict__ lnb,
                           const float* __restrict__ rout, float* __restrict__ o, int n)
{
    int row = blockIdx.x * 8 + (threadIdx.x >> 5);
    if (row >= n) return;
    int lane = threadIdx.x & 31;

    int beg = __ldg(rowptr + row);
    int end = __ldg(rowptr + row + 1);

    const float4* xwv = (const float4*)xw;
    float4 a0 = make_float4(0.f, 0.f, 0.f, 0.f);
    float4 a1 = make_float4(0.f, 0.f, 0.f, 0.f);
    int e = beg;
    for (; e + 2 <= end; e += 2) {
        int s0 = __ldg(csr + e);
        int s1 = __ldg(csr + e + 1);
        float4 v0 = __ldg(xwv + (size_t)s0 * 32 + lane);
        float4 v1 = __ldg(xwv + (size_t)s1 * 32 + lane);
        a0.x += v0.x; a0.y += v0.y; a0.z += v0.z; a0.w += v0.w;
        a1.x += v1.x; a1.y += v1.y; a1.z += v1.z; a1.w += v1.w;
    }
    if (e < end) {
        int s0 = __ldg(csr + e);
        float4 v0 = __ldg(xwv + (size_t)s0 * 32 + lane);
        a0.x += v0.x; a0.y += v0.y; a0.z += v0.z; a0.w += v0.w;
    }
    float4 acc = make_float4(a0.x + a1.x, a0.y + a1.y, a0.z + a1.z, a0.w + a1.w);

    float s = __ldg(rin + row);
    float4 bb = ((const float4*)bias)[lane];
    float4 f = __ldg((const float4*)feat + (size_t)row * 32 + lane);
    float4 h;
    h.x = fmaf(acc.x, s, bb.x) + RESC * f.x;
    h.y = fmaf(acc.y, s, bb.y) + RESC * f.y;
    h.z = fmaf(acc.z, s, bb.z) + RESC * f.z;
    h.w = fmaf(acc.w, s, bb.w) + RESC * f.w;

    if (!DO_LN) {
        ((float4*)(o + (size_t)row * DD))[lane] = h;
        return;
    }

    float sum = h.x + h.y + h.z + h.w;
#pragma unroll
    for (int off = 16; off > 0; off >>= 1) sum += __shfl_xor_sync(0xFFFFFFFFu, sum, off);
    float mu = sum * (1.0f / 128.0f);

    float dx = h.x - mu, dy = h.y - mu, dz = h.z - mu, dw = h.w - mu;
    float sq = dx * dx + dy * dy + dz * dz + dw * dw;
#pragma unroll
    for (int off = 16; off > 0; off >>= 1) sq += __shfl_xor_sync(0xFFFFFFFFu, sq, off);
    float inv = rsqrtf(sq * (1.0f / 128.0f) + LNEPS);

    float ro = __ldg(rout + row);
    float4 gg = ((const float4*)lng)[lane];
    float4 lb = ((const float4*)lnb)[lane];
    float4 r;
    r.x = fmaxf(fmaf(dx * inv, gg.x, lb.x), 0.0f) * ro;
    r.y = fmaxf(fmaf(dy * inv, gg.y, lb.y), 0.0f) * ro;
    r.z = fmaxf(fmaf(dz * inv, gg.z, lb.z), 0.0f) * ro;
    r.w = fmaxf(fmaf(dw * inv, gg.w, lb.w), 0.0f) * ro;
    ((float4*)(o + (size_t)row * DD))[lane] = r;
}

// ---------------- launch ------------------------------------------------------
extern "C" void kernel_launch(void* const* d_in, const int* in_sizes, int n_in,
                              void* d_out, int out_size)
{
    const int*   src     = (const int*)d_in[0];
    const int*   dst     = (const int*)d_in[1];
    const float* in_feat = (const float*)d_in[2];
    const float* W1      = (const float*)d_in[3];
    const float* b1      = (const float*)d_in[4];
    const float* W2      = (const float*)d_in[5];
    const float* b2      = (const float*)d_in[6];
    const float* ln1g    = (const float*)d_in[7];
    const float* ln1b    = (const float*)d_in[8];
    const float* ln2g    = (const float*)d_in[9];
    const float* ln2b    = (const float*)d_in[10];
    float* out = (float*)d_out;

    int E = in_sizes[0];
    int n = in_sizes[2] / DD;

    float *t, *xw, *rout, *rin;
    int *degout, *degin, *rowptr, *cursor, *csrsrc, *bsums;
    cudaGetSymbolAddress((void**)&t,      g_t);
    cudaGetSymbolAddress((void**)&xw,     g_xw);
    cudaGetSymbolAddress((void**)&rout,   g_rout);
    cudaGetSymbolAddress((void**)&rin,    g_rin);
    cudaGetSymbolAddress((void**)&degout, g_degout);
    cudaGetSymbolAddress((void**)&degin,  g_degin);
    cudaGetSymbolAddress((void**)&rowptr, g_rowptr);
    cudaGetSymbolAddress((void**)&cursor, g_cursor);
    cudaGetSymbolAddress((void**)&csrsrc, g_csrsrc);
    cudaGetSymbolAddress((void**)&bsums,  g_bsums);

    const int TB = 256;
    int gridE    = (E + TB - 1) / TB;
    int gridN    = (n + TB - 1) / TB;
    int gridRow  = (n + 7) / 8;
    int gridGemm = (n + 127) / 128;
    int gridScan = (n + 1023) / 1024;

    // ---- graph preprocessing (per call; deterministic)
    cudaMemsetAsync(degout, 0, n * sizeof(int));
    cudaMemsetAsync(degin,  0, n * sizeof(int));
    degree_kernel<<<gridE, TB>>>(src, dst, degout, degin, E);
    rsqrt_kernel<<<gridN, TB>>>(degout, degin, rout, rin, n);
    scan_block_kernel<<<gridScan, 256>>>(degin, rowptr, bsums, n);
    scan_spine_kernel<<<1, 128>>>(bsums, gridScan);
    scan_add_kernel<<<gridScan, 256>>>(rowptr, cursor, bsums, n, E);
    csr_fill_kernel<<<gridE, TB>>>(src, dst, cursor, csrsrc, E);

    // ---- conv1
    gemm_tf32_kernel<<<gridGemm, TB>>>(in_feat, W1, rout, xw, n);
    agg_kernel<true><<<gridRow, TB>>>(rowptr, csrsrc, xw, rin, b1, in_feat,
                                      ln1g, ln1b, rout, t, n);

    // ---- conv2
    gemm_tf32_kernel<<<gridGemm, TB>>>(t, W2, nullptr, xw, n);
    agg_kernel<true><<<gridRow, TB>>>(rowptr, csrsrc, xw, rin, b2, in_feat,
                                      ln2g, ln2b, rout, t, n);

    // ---- conv3
    gemm_tf32_kernel<<<gridGemm, TB>>>(t, W2, nullptr, xw, n);
    agg_kernel<false><<<gridRow, TB>>>(rowptr, csrsrc, xw, rin, b2, in_feat,
                                       nullptr, nullptr, nullptr, out, n);
}

// round 4
// speedup vs baseline: 3.4283x; 1.1242x over previous
#include <cuda_runtime.h>
#include <cuda_fp16.h>
#include <cstdint>

#define DD 128
#define NMAX 100000
#define EMAX 1600000
#define RESC 0.2f
#define LNEPS 1e-5f

// ---------------- scratch (static device globals; no allocs allowed) --------
__device__ float  g_t[NMAX * DD];      // GEMM input (LN'd features)
__device__ __half g_xw[NMAX * DD];     // GEMM output (pre-aggregation), fp16
__device__ float  g_rout[NMAX];        // rsqrt(deg_out)
__device__ float  g_rin[NMAX];         // rsqrt(deg_in)
__device__ int    g_degout[NMAX];
__device__ int    g_degin[NMAX];
__device__ int    g_rowptr[NMAX + 1];  // CSR by dst
__device__ int    g_cursor[NMAX];
__device__ int    g_csrsrc[EMAX];      // src ids grouped by dst
__device__ int    g_bsums[256];        // scan block sums

// ---------------- degree (int) ----------------------------------------------
__global__ void degree_kernel(const int* __restrict__ src, const int* __restrict__ dst,
                              int* __restrict__ dout, int* __restrict__ din, int e) {
    int i = blockIdx.x * blockDim.x + threadIdx.x;
    if (i < e) {
        atomicAdd(dout + src[i], 1);
        atomicAdd(din + dst[i], 1);
    }
}

__global__ void rsqrt_kernel(const int* __restrict__ dout, const int* __restrict__ din,
                             float* __restrict__ rout, float* __restrict__ rin, int n) {
    int i = blockIdx.x * blockDim.x + threadIdx.x;
    if (i < n) {
        rout[i] = rsqrtf((float)max(dout[i], 1));
        rin[i]  = rsqrtf((float)max(din[i], 1));
    }
}

// ---------------- 3-kernel exclusive scan (1024 elems / block) --------------
__global__ void scan_block_kernel(const int* __restrict__ in, int* __restrict__ out,
                                  int* __restrict__ bsums, int n) {
    __shared__ int wsum[8];
    int t = threadIdx.x;
    int lane = t & 31, wid = t >> 5;
    int base = blockIdx.x * 1024 + t * 4;

    int v0 = (base + 0 < n) ? in[base + 0] : 0;
    int v1 = (base + 1 < n) ? in[base + 1] : 0;
    int v2 = (base + 2 < n) ? in[base + 2] : 0;
    int v3 = (base + 3 < n) ? in[base + 3] : 0;
    int tsum = v0 + v1 + v2 + v3;

    int x = tsum;
#pragma unroll
    for (int o = 1; o < 32; o <<= 1) {
        int y = __shfl_up_sync(0xFFFFFFFFu, x, o);
        if (lane >= o) x += y;
    }
    if (lane == 31) wsum[wid] = x;
    __syncthreads();
    if (wid == 0) {
        int w = (lane < 8) ? wsum[lane] : 0;
        int orig = w;
#pragma unroll
        for (int o = 1; o < 8; o <<= 1) {
            int y = __shfl_up_sync(0xFFFFFFFFu, w, o);
            if (lane >= o) w += y;
        }
        if (lane < 8) wsum[lane] = w - orig;
    }
    __syncthreads();

    int texcl = wsum[wid] + x - tsum;
    if (base + 0 < n) out[base + 0] = texcl;
    if (base + 1 < n) out[base + 1] = texcl + v0;
    if (base + 2 < n) out[base + 2] = texcl + v0 + v1;
    if (base + 3 < n) out[base + 3] = texcl + v0 + v1 + v2;
    if (t == 255) bsums[blockIdx.x] = wsum[7] + x;
}

__global__ void scan_spine_kernel(int* __restrict__ bsums, int nb) {
    __shared__ int sh[128];
    int t = threadIdx.x;
    int v = (t < nb) ? bsums[t] : 0;
    int orig = v;
#pragma unroll
    for (int o = 1; o < 128; o <<= 1) {
        sh[t] = v;
        __syncthreads();
        int y = (t >= o) ? sh[t - o] : 0;
        __syncthreads();
        v += y;
    }
    if (t < nb) bsums[t] = v - orig;
}

__global__ void scan_add_kernel(int* __restrict__ out, int* __restrict__ cursor,
                                const int* __restrict__ bsums, int n, int e) {
    int base = blockIdx.x * 1024 + threadIdx.x * 4;
    int add = bsums[blockIdx.x];
#pragma unroll
    for (int i = 0; i < 4; i++)
        if (base + i < n) {
            int v = out[base + i] + add;
            out[base + i] = v;
            cursor[base + i] = v;
        }
    if (blockIdx.x == 0 && threadIdx.x == 0) out[n] = e;
}

__global__ void csr_fill_kernel(const int* __restrict__ src, const int* __restrict__ dst,
                                int* __restrict__ cursor, int* __restrict__ csr, int e) {
    int i = blockIdx.x * blockDim.x + threadIdx.x;
    if (i < e) {
        int p = atomicAdd(cursor + dst[i], 1);
        csr[p] = src[i];
    }
}

// ---------------- TF32 tensor-core GEMM, fp16 output -------------------------
// C[n,128] = (rs ? diag(rs) : I) A[n,128] @ W[128,128]
#define SST 136

__device__ __forceinline__ uint32_t f2tf32(float x) {
    uint32_t r;
    asm("cvt.rna.tf32.f32 %0, %1;" : "=r"(r) : "f"(x));
    return r;
}

__global__ __launch_bounds__(256) void gemm_tf32_kernel(
    const float* __restrict__ A, const float* __restrict__ W,
    const float* __restrict__ rs, __half* __restrict__ C, int n)
{
    __shared__ uint32_t sA[2][16 * SST];
    __shared__ uint32_t sW[2][16 * SST];

    int tid = threadIdx.x;
    int lane = tid & 31;
    int wrp = tid >> 5;
    int wm = wrp & 3;
    int wn = wrp >> 2;
    int tig = lane & 3;
    int gid = lane >> 2;
    int row0 = blockIdx.x * 128;

    int ar0 = tid >> 2;
    int ar1 = ar0 + 64;
    int ak0 = (tid & 3) << 2;
    int wk0 = tid >> 5;
    int wk1 = wk0 + 8;
    int wc4 = (tid & 31) << 2;

    bool rok0 = (row0 + ar0) < n;
    bool rok1 = (row0 + ar1) < n;
    float sc0 = 1.0f, sc1 = 1.0f;
    if (rs != nullptr) {
        if (rok0) sc0 = __ldg(rs + row0 + ar0);
        if (rok1) sc1 = __ldg(rs + row0 + ar1);
    }
    const float* Ap0 = A + (size_t)(row0 + ar0) * DD + ak0;
    const float* Ap1 = A + (size_t)(row0 + ar1) * DD + ak0;
    const float* Wp0 = W + (size_t)wk0 * DD + wc4;
    const float* Wp1 = W + (size_t)wk1 * DD + wc4;

    float acc[2][8][4];
#pragma unroll
    for (int i = 0; i < 2; i++)
#pragma unroll
        for (int j = 0; j < 8; j++)
#pragma unroll
            for (int k = 0; k < 4; k++) acc[i][j][k] = 0.0f;

    float4 a0 = make_float4(0.f, 0.f, 0.f, 0.f), a1 = a0;
    if (rok0) a0 = *(const float4*)Ap0;
    if (rok1) a1 = *(const float4*)Ap1;
    float4 w0 = *(const float4*)Wp0;
    float4 w1 = *(const float4*)Wp1;

    {
        uint32_t* pA = &sA[0][0];
        pA[(ak0 + 0) * SST + ar0] = f2tf32(a0.x * sc0);
        pA[(ak0 + 1) * SST + ar0] = f2tf32(a0.y * sc0);
        pA[(ak0 + 2) * SST + ar0] = f2tf32(a0.z * sc0);
        pA[(ak0 + 3) * SST + ar0] = f2tf32(a0.w * sc0);
        pA[(ak0 + 0) * SST + ar1] = f2tf32(a1.x * sc1);
        pA[(ak0 + 1) * SST + ar1] = f2tf32(a1.y * sc1);
        pA[(ak0 + 2) * SST + ar1] = f2tf32(a1.z * sc1);
        pA[(ak0 + 3) * SST + ar1] = f2tf32(a1.w * sc1);
        uint32_t* pW = &sW[0][0];
        uint4 u0 = make_uint4(f2tf32(w0.x), f2tf32(w0.y), f2tf32(w0.z), f2tf32(w0.w));
        uint4 u1 = make_uint4(f2tf32(w1.x), f2tf32(w1.y), f2tf32(w1.z), f2tf32(w1.w));
        *(uint4*)&pW[wk0 * SST + wc4] = u0;
        *(uint4*)&pW[wk1 * SST + wc4] = u1;
    }
    __syncthreads();

#pragma unroll
    for (int s = 0; s < 8; s++) {
        int cur = s & 1;
        if (s < 7) {
            int kb = (s + 1) * 16;
            a0 = make_float4(0.f, 0.f, 0.f, 0.f); a1 = a0;
            if (rok0) a0 = *(const float4*)(Ap0 + kb);
            if (rok1) a1 = *(const float4*)(Ap1 + kb);
            w0 = *(const float4*)(Wp0 + (size_t)kb * DD);
            w1 = *(const float4*)(Wp1 + (size_t)kb * DD);
        }

        const uint32_t* pA = &sA[cur][0];
        const uint32_t* pW = &sW[cur][0];
#pragma unroll
        for (int ks = 0; ks < 2; ks++) {
            int k0 = ks * 8;
            uint32_t af[2][4];
#pragma unroll
            for (int mt = 0; mt < 2; mt++) {
                int rb = wm * 32 + mt * 16 + gid;
                af[mt][0] = pA[(k0 + tig) * SST + rb];
                af[mt][1] = pA[(k0 + tig) * SST + rb + 8];
                af[mt][2] = pA[(k0 + tig + 4) * SST + rb];
                af[mt][3] = pA[(k0 + tig + 4) * SST + rb + 8];
            }
#pragma unroll
            for (int nt = 0; nt < 8; nt++) {
                int cb = wn * 64 + nt * 8 + gid;
                uint32_t b0 = pW[(k0 + tig) * SST + cb];
                uint32_t b1 = pW[(k0 + tig + 4) * SST + cb];
#pragma unroll
                for (int mt = 0; mt < 2; mt++) {
                    asm volatile(
                        "mma.sync.aligned.m16n8k8.row.col.f32.tf32.tf32.f32 "
                        "{%0,%1,%2,%3}, {%4,%5,%6,%7}, {%8,%9}, {%0,%1,%2,%3};"
                        : "+f"(acc[mt][nt][0]), "+f"(acc[mt][nt][1]),
                          "+f"(acc[mt][nt][2]), "+f"(acc[mt][nt][3])
                        : "r"(af[mt][0]), "r"(af[mt][1]), "r"(af[mt][2]), "r"(af[mt][3]),
                          "r"(b0), "r"(b1));
                }
            }
        }

        if (s < 7) {
            int nb = cur ^ 1;
            uint32_t* qA = &sA[nb][0];
            qA[(ak0 + 0) * SST + ar0] = f2tf32(a0.x * sc0);
            qA[(ak0 + 1) * SST + ar0] = f2tf32(a0.y * sc0);
            qA[(ak0 + 2) * SST + ar0] = f2tf32(a0.z * sc0);
            qA[(ak0 + 3) * SST + ar0] = f2tf32(a0.w * sc0);
            qA[(ak0 + 0) * SST + ar1] = f2tf32(a1.x * sc1);
            qA[(ak0 + 1) * SST + ar1] = f2tf32(a1.y * sc1);
            qA[(ak0 + 2) * SST + ar1] = f2tf32(a1.z * sc1);
            qA[(ak0 + 3) * SST + ar1] = f2tf32(a1.w * sc1);
            uint32_t* qW = &sW[nb][0];
            uint4 u0 = make_uint4(f2tf32(w0.x), f2tf32(w0.y), f2tf32(w0.z), f2tf32(w0.w));
            uint4 u1 = make_uint4(f2tf32(w1.x), f2tf32(w1.y), f2tf32(w1.z), f2tf32(w1.w));
            *(uint4*)&qW[wk0 * SST + wc4] = u0;
            *(uint4*)&qW[wk1 * SST + wc4] = u1;
            __syncthreads();
        }
    }

    // writeout (fp16)
#pragma unroll
    for (int mt = 0; mt < 2; mt++) {
        int r0 = row0 + wm * 32 + mt * 16 + gid;
        int r1 = r0 + 8;
#pragma unroll
        for (int nt = 0; nt < 8; nt++) {
            int col = wn * 64 + nt * 8 + tig * 2;
            if (r0 < n)
                *(__half2*)(C + (size_t)r0 * DD + col) =
                    __floats2half2_rn(acc[mt][nt][0], acc[mt][nt][1]);
            if (r1 < n)
                *(__half2*)(C + (size_t)r1 * DD + col) =
                    __floats2half2_rn(acc[mt][nt][2], acc[mt][nt][3]);
        }
    }
}

// ---------------- fused CSR aggregate (fp16 gather) + epilogue [+LN] --------
template <bool DO_LN>
__global__ void agg_kernel(const int* __restrict__ rowptr, const int* __restrict__ csr,
                           const __half* __restrict__ xw, const float* __restrict__ rin,
                           const float* __restrict__ bias, const float* __restrict__ feat,
                           const float* __restrict__ lng, const float* __restrict__ lnb,
                           const float* __restrict__ rout, float* __restrict__ o, int n)
{
    int row = blockIdx.x * 8 + (threadIdx.x >> 5);
    if (row >= n) return;
    int lane = threadIdx.x & 31;

    int beg = __ldg(rowptr + row);
    int end = __ldg(rowptr + row + 1);

    const uint2* xwv = (const uint2*)xw;  // 4 halves per lane; row = 32 uint2
    float ax = 0.f, ay = 0.f, az = 0.f, aw = 0.f;

    int e = beg;
    for (; e + 4 <= end; e += 4) {
        int s0 = __ldg(csr + e);
        int s1 = __ldg(csr + e + 1);
        int s2 = __ldg(csr + e + 2);
        int s3 = __ldg(csr + e + 3);
        uint2 u0 = __ldg(xwv + (size_t)s0 * 32 + lane);
        uint2 u1 = __ldg(xwv + (size_t)s1 * 32 + lane);
        uint2 u2 = __ldg(xwv + (size_t)s2 * 32 + lane);
        uint2 u3 = __ldg(xwv + (size_t)s3 * 32 + lane);
#pragma unroll
        for (int q = 0; q < 4; q++) {
            uint2 u = (q == 0) ? u0 : (q == 1) ? u1 : (q == 2) ? u2 : u3;
            float2 lo = __half22float2(*(const __half2*)&u.x);
            float2 hi = __half22float2(*(const __half2*)&u.y);
            ax += lo.x; ay += lo.y; az += hi.x; aw += hi.y;
        }
    }
    for (; e < end; e++) {
        int s0 = __ldg(csr + e);
        uint2 u = __ldg(xwv + (size_t)s0 * 32 + lane);
        float2 lo = __half22float2(*(const __half2*)&u.x);
        float2 hi = __half22float2(*(const __half2*)&u.y);
        ax += lo.x; ay += lo.y; az += hi.x; aw += hi.y;
    }

    float s = __ldg(rin + row);
    float4 bb = ((const float4*)bias)[lane];
    float4 f = __ldg((const float4*)feat + (size_t)row * 32 + lane);
    float4 h;
    h.x = fmaf(ax, s, bb.x) + RESC * f.x;
    h.y = fmaf(ay, s, bb.y) + RESC * f.y;
    h.z = fmaf(az, s, bb.z) + RESC * f.z;
    h.w = fmaf(aw, s, bb.w) + RESC * f.w;

    if (!DO_LN) {
        ((float4*)(o + (size_t)row * DD))[lane] = h;
        return;
    }

    float sum = h.x + h.y + h.z + h.w;
#pragma unroll
    for (int off = 16; off > 0; off >>= 1) sum += __shfl_xor_sync(0xFFFFFFFFu, sum, off);
    float mu = sum * (1.0f / 128.0f);

    float dx = h.x - mu, dy = h.y - mu, dz = h.z - mu, dw = h.w - mu;
    float sq = dx * dx + dy * dy + dz * dz + dw * dw;
#pragma unroll
    for (int off = 16; off > 0; off >>= 1) sq += __shfl_xor_sync(0xFFFFFFFFu, sq, off);
    float inv = rsqrtf(sq * (1.0f / 128.0f) + LNEPS);

    float ro = __ldg(rout + row);
    float4 gg = ((const float4*)lng)[lane];
    float4 lb = ((const float4*)lnb)[lane];
    float4 r;
    r.x = fmaxf(fmaf(dx * inv, gg.x, lb.x), 0.0f) * ro;
    r.y = fmaxf(fmaf(dy * inv, gg.y, lb.y), 0.0f) * ro;
    r.z = fmaxf(fmaf(dz * inv, gg.z, lb.z), 0.0f) * ro;
    r.w = fmaxf(fmaf(dw * inv, gg.w, lb.w), 0.0f) * ro;
    ((float4*)(o + (size_t)row * DD))[lane] = r;
}

// ---------------- launch ------------------------------------------------------
extern "C" void kernel_launch(void* const* d_in, const int* in_sizes, int n_in,
                              void* d_out, int out_size)
{
    const int*   src     = (const int*)d_in[0];
    const int*   dst     = (const int*)d_in[1];
    const float* in_feat = (const float*)d_in[2];
    const float* W1      = (const float*)d_in[3];
    const float* b1      = (const float*)d_in[4];
    const float* W2      = (const float*)d_in[5];
    const float* b2      = (const float*)d_in[6];
    const float* ln1g    = (const float*)d_in[7];
    const float* ln1b    = (const float*)d_in[8];
    const float* ln2g    = (const float*)d_in[9];
    const float* ln2b    = (const float*)d_in[10];
    float* out = (float*)d_out;

    int E = in_sizes[0];
    int n = in_sizes[2] / DD;

    float *t, *rout, *rin;
    __half* xw;
    int *degout, *degin, *rowptr, *cursor, *csrsrc, *bsums;
    cudaGetSymbolAddress((void**)&t,      g_t);
    cudaGetSymbolAddress((void**)&xw,     g_xw);
    cudaGetSymbolAddress((void**)&rout,   g_rout);
    cudaGetSymbolAddress((void**)&rin,    g_rin);
    cudaGetSymbolAddress((void**)&degout, g_degout);
    cudaGetSymbolAddress((void**)&degin,  g_degin);
    cudaGetSymbolAddress((void**)&rowptr, g_rowptr);
    cudaGetSymbolAddress((void**)&cursor, g_cursor);
    cudaGetSymbolAddress((void**)&csrsrc, g_csrsrc);
    cudaGetSymbolAddress((void**)&bsums,  g_bsums);

    const int TB = 256;
    int gridE    = (E + TB - 1) / TB;
    int gridN    = (n + TB - 1) / TB;
    int gridRow  = (n + 7) / 8;
    int gridGemm = (n + 127) / 128;
    int gridScan = (n + 1023) / 1024;

    // ---- graph preprocessing (per call; deterministic)
    cudaMemsetAsync(degout, 0, n * sizeof(int));
    cudaMemsetAsync(degin,  0, n * sizeof(int));
    degree_kernel<<<gridE, TB>>>(src, dst, degout, degin, E);
    rsqrt_kernel<<<gridN, TB>>>(degout, degin, rout, rin, n);
    scan_block_kernel<<<gridScan, 256>>>(degin, rowptr, bsums, n);
    scan_spine_kernel<<<1, 128>>>(bsums, gridScan);
    scan_add_kernel<<<gridScan, 256>>>(rowptr, cursor, bsums, n, E);
    csr_fill_kernel<<<gridE, TB>>>(src, dst, cursor, csrsrc, E);

    // ---- conv1
    gemm_tf32_kernel<<<gridGemm, TB>>>(in_feat, W1, rout, xw, n);
    agg_kernel<true><<<gridRow, TB>>>(rowptr, csrsrc, xw, rin, b1, in_feat,
                                      ln1g, ln1b, rout, t, n);

    // ---- conv2
    gemm_tf32_kernel<<<gridGemm, TB>>>(t, W2, nullptr, xw, n);
    agg_kernel<true><<<gridRow, TB>>>(rowptr, csrsrc, xw, rin, b2, in_feat,
                                      ln2g, ln2b, rout, t, n);

    // ---- conv3
    gemm_tf32_kernel<<<gridGemm, TB>>>(t, W2, nullptr, xw, n);
    agg_kernel<false><<<gridRow, TB>>>(rowptr, csrsrc, xw, rin, b2, in_feat,
                                       nullptr, nullptr, nullptr, out, n);
}

// round 5
// speedup vs baseline: 3.5496x; 1.0354x over previous
#include <cuda_runtime.h>
#include <cuda_fp16.h>
#include <cstdint>

#define DD 128
#define NMAX 100000
#define EMAX 1600000
#define RESC 0.2f
#define LNEPS 1e-5f

// ---------------- scratch (static device globals; no allocs allowed) --------
__device__ __half g_t[NMAX * DD];      // GEMM input (LN'd features), fp16
__device__ __half g_xw[NMAX * DD];     // GEMM output (pre-aggregation), fp16
__device__ float  g_rout[NMAX];
__device__ float  g_rin[NMAX];
__device__ int    g_degout[NMAX];
__device__ int    g_degin[NMAX];
__device__ int    g_rowptr[NMAX + 1];
__device__ int    g_cursor[NMAX];
__device__ int    g_csrsrc[EMAX];
__device__ int    g_bsums[256];

// ---------------- degree (int) ----------------------------------------------
__global__ void degree_kernel(const int* __restrict__ src, const int* __restrict__ dst,
                              int* __restrict__ dout, int* __restrict__ din, int e) {
    int i = blockIdx.x * blockDim.x + threadIdx.x;
    if (i < e) {
        atomicAdd(dout + src[i], 1);
        atomicAdd(din + dst[i], 1);
    }
}

__global__ void rsqrt_kernel(const int* __restrict__ dout, const int* __restrict__ din,
                             float* __restrict__ rout, float* __restrict__ rin, int n) {
    int i = blockIdx.x * blockDim.x + threadIdx.x;
    if (i < n) {
        rout[i] = rsqrtf((float)max(dout[i], 1));
        rin[i]  = rsqrtf((float)max(din[i], 1));
    }
}

// ---------------- 3-kernel exclusive scan ------------------------------------
__global__ void scan_block_kernel(const int* __restrict__ in, int* __restrict__ out,
                                  int* __restrict__ bsums, int n) {
    __shared__ int wsum[8];
    int t = threadIdx.x;
    int lane = t & 31, wid = t >> 5;
    int base = blockIdx.x * 1024 + t * 4;

    int v0 = (base + 0 < n) ? in[base + 0] : 0;
    int v1 = (base + 1 < n) ? in[base + 1] : 0;
    int v2 = (base + 2 < n) ? in[base + 2] : 0;
    int v3 = (base + 3 < n) ? in[base + 3] : 0;
    int tsum = v0 + v1 + v2 + v3;

    int x = tsum;
#pragma unroll
    for (int o = 1; o < 32; o <<= 1) {
        int y = __shfl_up_sync(0xFFFFFFFFu, x, o);
        if (lane >= o) x += y;
    }
    if (lane == 31) wsum[wid] = x;
    __syncthreads();
    if (wid == 0) {
        int w = (lane < 8) ? wsum[lane] : 0;
        int orig = w;
#pragma unroll
        for (int o = 1; o < 8; o <<= 1) {
            int y = __shfl_up_sync(0xFFFFFFFFu, w, o);
            if (lane >= o) w += y;
        }
        if (lane < 8) wsum[lane] = w - orig;
    }
    __syncthreads();

    int texcl = wsum[wid] + x - tsum;
    if (base + 0 < n) out[base + 0] = texcl;
    if (base + 1 < n) out[base + 1] = texcl + v0;
    if (base + 2 < n) out[base + 2] = texcl + v0 + v1;
    if (base + 3 < n) out[base + 3] = texcl + v0 + v1 + v2;
    if (t == 255) bsums[blockIdx.x] = wsum[7] + x;
}

__global__ void scan_spine_kernel(int* __restrict__ bsums, int nb) {
    __shared__ int sh[128];
    int t = threadIdx.x;
    int v = (t < nb) ? bsums[t] : 0;
    int orig = v;
#pragma unroll
    for (int o = 1; o < 128; o <<= 1) {
        sh[t] = v;
        __syncthreads();
        int y = (t >= o) ? sh[t - o] : 0;
        __syncthreads();
        v += y;
    }
    if (t < nb) bsums[t] = v - orig;
}

__global__ void scan_add_kernel(int* __restrict__ out, int* __restrict__ cursor,
                                const int* __restrict__ bsums, int n, int e) {
    int base = blockIdx.x * 1024 + threadIdx.x * 4;
    int add = bsums[blockIdx.x];
#pragma unroll
    for (int i = 0; i < 4; i++)
        if (base + i < n) {
            int v = out[base + i] + add;
            out[base + i] = v;
            cursor[base + i] = v;
        }
    if (blockIdx.x == 0 && threadIdx.x == 0) out[n] = e;
}

__global__ void csr_fill_kernel(const int* __restrict__ src, const int* __restrict__ dst,
                                int* __restrict__ cursor, int* __restrict__ csr, int e) {
    int i = blockIdx.x * blockDim.x + threadIdx.x;
    if (i < e) {
        int p = atomicAdd(cursor + dst[i], 1);
        csr[p] = src[i];
    }
}

// ---------------- TF32 tensor-core GEMM, templated A type, fp16 output -------
#define SST 136

__device__ __forceinline__ uint32_t f2tf32(float x) {
    uint32_t r;
    asm("cvt.rna.tf32.f32 %0, %1;" : "=r"(r) : "f"(x));
    return r;
}

__device__ __forceinline__ float4 ld4(const float* p) {
    return *(const float4*)p;
}
__device__ __forceinline__ float4 ld4(const __half* p) {
    uint2 u = *(const uint2*)p;
    float2 lo = __half22float2(*(const __half2*)&u.x);
    float2 hi = __half22float2(*(const __half2*)&u.y);
    return make_float4(lo.x, lo.y, hi.x, hi.y);
}

template <typename AT>
__global__ __launch_bounds__(256) void gemm_tf32_kernel(
    const AT* __restrict__ A, const float* __restrict__ W,
    const float* __restrict__ rs, __half* __restrict__ C, int n)
{
    __shared__ uint32_t sA[2][16 * SST];
    __shared__ uint32_t sW[2][16 * SST];

    int tid = threadIdx.x;
    int lane = tid & 31;
    int wrp = tid >> 5;
    int wm = wrp & 3;
    int wn = wrp >> 2;
    int tig = lane & 3;
    int gid = lane >> 2;
    int row0 = blockIdx.x * 128;

    int ar0 = tid >> 2;
    int ar1 = ar0 + 64;
    int ak0 = (tid & 3) << 2;
    int wk0 = tid >> 5;
    int wk1 = wk0 + 8;
    int wc4 = (tid & 31) << 2;

    bool rok0 = (row0 + ar0) < n;
    bool rok1 = (row0 + ar1) < n;
    float sc0 = 1.0f, sc1 = 1.0f;
    if (rs != nullptr) {
        if (rok0) sc0 = __ldg(rs + row0 + ar0);
        if (rok1) sc1 = __ldg(rs + row0 + ar1);
    }
    const AT* Ap0 = A + (size_t)(row0 + ar0) * DD + ak0;
    const AT* Ap1 = A + (size_t)(row0 + ar1) * DD + ak0;
    const float* Wp0 = W + (size_t)wk0 * DD + wc4;
    const float* Wp1 = W + (size_t)wk1 * DD + wc4;

    float acc[2][8][4];
#pragma unroll
    for (int i = 0; i < 2; i++)
#pragma unroll
        for (int j = 0; j < 8; j++)
#pragma unroll
            for (int k = 0; k < 4; k++) acc[i][j][k] = 0.0f;

    float4 a0 = make_float4(0.f, 0.f, 0.f, 0.f), a1 = a0;
    if (rok0) a0 = ld4(Ap0);
    if (rok1) a1 = ld4(Ap1);
    float4 w0 = ld4(Wp0);
    float4 w1 = ld4(Wp1);

    {
        uint32_t* pA = &sA[0][0];
        pA[(ak0 + 0) * SST + ar0] = f2tf32(a0.x * sc0);
        pA[(ak0 + 1) * SST + ar0] = f2tf32(a0.y * sc0);
        pA[(ak0 + 2) * SST + ar0] = f2tf32(a0.z * sc0);
        pA[(ak0 + 3) * SST + ar0] = f2tf32(a0.w * sc0);
        pA[(ak0 + 0) * SST + ar1] = f2tf32(a1.x * sc1);
        pA[(ak0 + 1) * SST + ar1] = f2tf32(a1.y * sc1);
        pA[(ak0 + 2) * SST + ar1] = f2tf32(a1.z * sc1);
        pA[(ak0 + 3) * SST + ar1] = f2tf32(a1.w * sc1);
        uint32_t* pW = &sW[0][0];
        uint4 u0 = make_uint4(f2tf32(w0.x), f2tf32(w0.y), f2tf32(w0.z), f2tf32(w0.w));
        uint4 u1 = make_uint4(f2tf32(w1.x), f2tf32(w1.y), f2tf32(w1.z), f2tf32(w1.w));
        *(uint4*)&pW[wk0 * SST + wc4] = u0;
        *(uint4*)&pW[wk1 * SST + wc4] = u1;
    }
    __syncthreads();

#pragma unroll
    for (int s = 0; s < 8; s++) {
        int cur = s & 1;
        if (s < 7) {
            int kb = (s + 1) * 16;
            a0 = make_float4(0.f, 0.f, 0.f, 0.f); a1 = a0;
            if (rok0) a0 = ld4(Ap0 + kb);
            if (rok1) a1 = ld4(Ap1 + kb);
            w0 = ld4(Wp0 + (size_t)kb * DD);
            w1 = ld4(Wp1 + (size_t)kb * DD);
        }

        const uint32_t* pA = &sA[cur][0];
        const uint32_t* pW = &sW[cur][0];
#pragma unroll
        for (int ks = 0; ks < 2; ks++) {
            int k0 = ks * 8;
            uint32_t af[2][4];
#pragma unroll
            for (int mt = 0; mt < 2; mt++) {
                int rb = wm * 32 + mt * 16 + gid;
                af[mt][0] = pA[(k0 + tig) * SST + rb];
                af[mt][1] = pA[(k0 + tig) * SST + rb + 8];
                af[mt][2] = pA[(k0 + tig + 4) * SST + rb];
                af[mt][3] = pA[(k0 + tig + 4) * SST + rb + 8];
            }
#pragma unroll
            for (int nt = 0; nt < 8; nt++) {
                int cb = wn * 64 + nt * 8 + gid;
                uint32_t b0 = pW[(k0 + tig) * SST + cb];
                uint32_t b1 = pW[(k0 + tig + 4) * SST + cb];
#pragma unroll
                for (int mt = 0; mt < 2; mt++) {
                    asm volatile(
                        "mma.sync.aligned.m16n8k8.row.col.f32.tf32.tf32.f32 "
                        "{%0,%1,%2,%3}, {%4,%5,%6,%7}, {%8,%9}, {%0,%1,%2,%3};"
                        : "+f"(acc[mt][nt][0]), "+f"(acc[mt][nt][1]),
                          "+f"(acc[mt][nt][2]), "+f"(acc[mt][nt][3])
                        : "r"(af[mt][0]), "r"(af[mt][1]), "r"(af[mt][2]), "r"(af[mt][3]),
                          "r"(b0), "r"(b1));
                }
            }
        }

        if (s < 7) {
            int nb = cur ^ 1;
            uint32_t* qA = &sA[nb][0];
            qA[(ak0 + 0) * SST + ar0] = f2tf32(a0.x * sc0);
            qA[(ak0 + 1) * SST + ar0] = f2tf32(a0.y * sc0);
            qA[(ak0 + 2) * SST + ar0] = f2tf32(a0.z * sc0);
            qA[(ak0 + 3) * SST + ar0] = f2tf32(a0.w * sc0);
            qA[(ak0 + 0) * SST + ar1] = f2tf32(a1.x * sc1);
            qA[(ak0 + 1) * SST + ar1] = f2tf32(a1.y * sc1);
            qA[(ak0 + 2) * SST + ar1] = f2tf32(a1.z * sc1);
            qA[(ak0 + 3) * SST + ar1] = f2tf32(a1.w * sc1);
            uint32_t* qW = &sW[nb][0];
            uint4 u0 = make_uint4(f2tf32(w0.x), f2tf32(w0.y), f2tf32(w0.z), f2tf32(w0.w));
            uint4 u1 = make_uint4(f2tf32(w1.x), f2tf32(w1.y), f2tf32(w1.z), f2tf32(w1.w));
            *(uint4*)&qW[wk0 * SST + wc4] = u0;
            *(uint4*)&qW[wk1 * SST + wc4] = u1;
            __syncthreads();
        }
    }

#pragma unroll
    for (int mt = 0; mt < 2; mt++) {
        int r0 = row0 + wm * 32 + mt * 16 + gid;
        int r1 = r0 + 8;
#pragma unroll
        for (int nt = 0; nt < 8; nt++) {
            int col = wn * 64 + nt * 8 + tig * 2;
            if (r0 < n)
                *(__half2*)(C + (size_t)r0 * DD + col) =
                    __floats2half2_rn(acc[mt][nt][0], acc[mt][nt][1]);
            if (r1 < n)
                *(__half2*)(C + (size_t)r1 * DD + col) =
                    __floats2half2_rn(acc[mt][nt][2], acc[mt][nt][3]);
        }
    }
}

// ---------------- fused CSR aggregate (fp16, deep-MLP) + epilogue [+LN] -----
__device__ __forceinline__ void acc_u2(uint2 u, float& ax, float& ay, float& az, float& aw) {
    float2 lo = __half22float2(*(const __half2*)&u.x);
    float2 hi = __half22float2(*(const __half2*)&u.y);
    ax += lo.x; ay += lo.y; az += hi.x; aw += hi.y;
}

template <bool DO_LN, typename OT>
__global__ void agg_kernel(const int* __restrict__ rowptr, const int* __restrict__ csr,
                           const __half* __restrict__ xw, const float* __restrict__ rin,
                           const float* __restrict__ bias, const float* __restrict__ feat,
                           const float* __restrict__ lng, const float* __restrict__ lnb,
                           const float* __restrict__ rout, OT* __restrict__ o, int n)
{
    int row = blockIdx.x * 8 + (threadIdx.x >> 5);
    if (row >= n) return;
    int lane = threadIdx.x & 31;

    int beg = __ldg(rowptr + row);
    int end = __ldg(rowptr + row + 1);

    const uint2* xwv = (const uint2*)xw + lane;
    float ax = 0.f, ay = 0.f, az = 0.f, aw = 0.f;

    int e = beg;
    // 8-wide batches: issue all loads before consuming
    for (; e + 8 <= end; e += 8) {
        int s[8];
#pragma unroll
        for (int q = 0; q < 8; q++) s[q] = __ldg(csr + e + q);
        uint2 u[8];
#pragma unroll
        for (int q = 0; q < 8; q++) u[q] = __ldg(xwv + (size_t)s[q] * 32);
#pragma unroll
        for (int q = 0; q < 8; q++) acc_u2(u[q], ax, ay, az, aw);
    }
    if (e + 4 <= end) {
        int s[4];
#pragma unroll
        for (int q = 0; q < 4; q++) s[q] = __ldg(csr + e + q);
        uint2 u[4];
#pragma unroll
        for (int q = 0; q < 4; q++) u[q] = __ldg(xwv + (size_t)s[q] * 32);
#pragma unroll
        for (int q = 0; q < 4; q++) acc_u2(u[q], ax, ay, az, aw);
        e += 4;
    }
    if (e + 2 <= end) {
        int s0 = __ldg(csr + e), s1 = __ldg(csr + e + 1);
        uint2 u0 = __ldg(xwv + (size_t)s0 * 32);
        uint2 u1 = __ldg(xwv + (size_t)s1 * 32);
        acc_u2(u0, ax, ay, az, aw);
        acc_u2(u1, ax, ay, az, aw);
        e += 2;
    }
    if (e < end) {
        int s0 = __ldg(csr + e);
        acc_u2(__ldg(xwv + (size_t)s0 * 32), ax, ay, az, aw);
    }

    float s = __ldg(rin + row);
    float4 bb = ((const float4*)bias)[lane];
    float4 f = __ldg((const float4*)feat + (size_t)row * 32 + lane);
    float4 h;
    h.x = fmaf(ax, s, bb.x) + RESC * f.x;
    h.y = fmaf(ay, s, bb.y) + RESC * f.y;
    h.z = fmaf(az, s, bb.z) + RESC * f.z;
    h.w = fmaf(aw, s, bb.w) + RESC * f.w;

    if (!DO_LN) {
        // final layer: fp32 out
        ((float4*)((float*)o + (size_t)row * DD))[lane] = h;
        return;
    }

    float sum = h.x + h.y + h.z + h.w;
#pragma unroll
    for (int off = 16; off > 0; off >>= 1) sum += __shfl_xor_sync(0xFFFFFFFFu, sum, off);
    float mu = sum * (1.0f / 128.0f);

    float dx = h.x - mu, dy = h.y - mu, dz = h.z - mu, dw = h.w - mu;
    float sq = dx * dx + dy * dy + dz * dz + dw * dw;
#pragma unroll
    for (int off = 16; off > 0; off >>= 1) sq += __shfl_xor_sync(0xFFFFFFFFu, sq, off);
    float inv = rsqrtf(sq * (1.0f / 128.0f) + LNEPS);

    float ro = __ldg(rout + row);
    float4 gg = ((const float4*)lng)[lane];
    float4 lb = ((const float4*)lnb)[lane];
    float rx = fmaxf(fmaf(dx * inv, gg.x, lb.x), 0.0f) * ro;
    float ry = fmaxf(fmaf(dy * inv, gg.y, lb.y), 0.0f) * ro;
    float rz = fmaxf(fmaf(dz * inv, gg.z, lb.z), 0.0f) * ro;
    float rw = fmaxf(fmaf(dw * inv, gg.w, lb.w), 0.0f) * ro;
    // fp16 write (4 halves per lane)
    uint2 w;
    *(__half2*)&w.x = __floats2half2_rn(rx, ry);
    *(__half2*)&w.y = __floats2half2_rn(rz, rw);
    ((uint2*)((__half*)o + (size_t)row * DD))[lane] = w;
}

// ---------------- launch ------------------------------------------------------
extern "C" void kernel_launch(void* const* d_in, const int* in_sizes, int n_in,
                              void* d_out, int out_size)
{
    const int*   src     = (const int*)d_in[0];
    const int*   dst     = (const int*)d_in[1];
    const float* in_feat = (const float*)d_in[2];
    const float* W1      = (const float*)d_in[3];
    const float* b1      = (const float*)d_in[4];
    const float* W2      = (const float*)d_in[5];
    const float* b2      = (const float*)d_in[6];
    const float* ln1g    = (const float*)d_in[7];
    const float* ln1b    = (const float*)d_in[8];
    const float* ln2g    = (const float*)d_in[9];
    const float* ln2b    = (const float*)d_in[10];
    float* out = (float*)d_out;

    int E = in_sizes[0];
    int n = in_sizes[2] / DD;

    __half *t, *xw;
    float *rout, *rin;
    int *degout, *degin, *rowptr, *cursor, *csrsrc, *bsums;
    cudaGetSymbolAddress((void**)&t,      g_t);
    cudaGetSymbolAddress((void**)&xw,     g_xw);
    cudaGetSymbolAddress((void**)&rout,   g_rout);
    cudaGetSymbolAddress((void**)&rin,    g_rin);
    cudaGetSymbolAddress((void**)&degout, g_degout);
    cudaGetSymbolAddress((void**)&degin,  g_degin);
    cudaGetSymbolAddress((void**)&rowptr, g_rowptr);
    cudaGetSymbolAddress((void**)&cursor, g_cursor);
    cudaGetSymbolAddress((void**)&csrsrc, g_csrsrc);
    cudaGetSymbolAddress((void**)&bsums,  g_bsums);

    const int TB = 256;
    int gridE    = (E + TB - 1) / TB;
    int gridN    = (n + TB - 1) / TB;
    int gridRow  = (n + 7) / 8;
    int gridGemm = (n + 127) / 128;
    int gridScan = (n + 1023) / 1024;

    cudaMemsetAsync(degout, 0, n * sizeof(int));
    cudaMemsetAsync(degin,  0, n * sizeof(int));
    degree_kernel<<<gridE, TB>>>(src, dst, degout, degin, E);
    rsqrt_kernel<<<gridN, TB>>>(degout, degin, rout, rin, n);
    scan_block_kernel<<<gridScan, 256>>>(degin, rowptr, bsums, n);
    scan_spine_kernel<<<1, 128>>>(bsums, gridScan);
    scan_add_kernel<<<gridScan, 256>>>(rowptr, cursor, bsums, n, E);
    csr_fill_kernel<<<gridE, TB>>>(src, dst, cursor, csrsrc, E);

    // ---- conv1 (A fp32 + rout scale)
    gemm_tf32_kernel<float><<<gridGemm, TB>>>(in_feat, W1, rout, xw, n);
    agg_kernel<true, __half><<<gridRow, TB>>>(rowptr, csrsrc, xw, rin, b1, in_feat,
                                              ln1g, ln1b, rout, t, n);

    // ---- conv2 (A fp16)
    gemm_tf32_kernel<__half><<<gridGemm, TB>>>(t, W2, nullptr, xw, n);
    agg_kernel<true, __half><<<gridRow, TB>>>(rowptr, csrsrc, xw, rin, b2, in_feat,
                                              ln2g, ln2b, rout, t, n);

    // ---- conv3
    gemm_tf32_kernel<__half><<<gridGemm, TB>>>(t, W2, nullptr, xw, n);
    agg_kernel<false, float><<<gridRow, TB>>>(rowptr, csrsrc, xw, rin, b2, in_feat,
                                              nullptr, nullptr, nullptr, out, n);
}